// round 14
// baseline (speedup 1.0000x reference)
#include <cuda_runtime.h>
#include <cuda_fp16.h>
#include <cstdint>
#include <cstddef>

// ============================================================================
// ImprovedGraphSAGE via portable mma.sync (HMMA) — sm_100-safe (no tcgen05).
//   p_mma_kernel : P = Xin @ Wih^T + (bih+bhh)  (HMMA, fp16 store)
//                  gates i,f,o PRE-SCALED by 0.5 (sigmoid-via-tanh trick)
//   lstm_mma     : 16-step LSTM; H @ Whh^T on HMMA; fused projections.
// R14: R11/R13 geometry (MCTA=144, 48x32 tiles, grid=139 single wave) with
//      BOTH tmp and c packed as half2 -> carried state 96 regs, no spill.
//      c updated in fp32 every step, stored fp16 (error damped by sig(f)).
// ============================================================================

#define NN   20000
#define DEG  16
#define FDIM 128

#define MCTA    144                        // nodes per CTA
#define NCTA2   ((NN + MCTA - 1) / MCTA)   // 139  (<= 148 SMs: one wave)
#define LTH     384                        // 12 warps: 3 rowgroups x 4 colgroups
#define ROWSTR  272                        // fp16 row stride bytes (ldmatrix-safe)
#define HTILE_B (MCTA * ROWSTR)            // 39168
#define WTILE_B (128 * ROWSTR)             // 34816

// lstm SMEM map
#define SM_H0   1024
#define SM_H1   (SM_H0 + HTILE_B)          // 40192
#define SM_W    (SM_H1 + HTILE_B)          // 79360
#define SMEM_L  (SM_W + 4 * WTILE_B)       // 218624  (< 227KB)

// p_mma SMEM map
#define SM_X    1024
#define SM_PW   (SM_X + HTILE_B)           // 40192
#define SMEM_PM (SM_PW + 4 * WTILE_B)      // 179456

__device__ __half g_P16[(size_t)NN * 512];
__device__ float  g_XA [(size_t)NN * FDIM];
__device__ float  g_XB [(size_t)NN * FDIM];

// ---------------------------------------------------------------------------
__device__ __forceinline__ uint32_t smem_u32(const void* p) {
    uint32_t a;
    asm("{ .reg .u64 t; cvta.to.shared.u64 t, %1; cvt.u32.u64 %0, t; }"
        : "=r"(a) : "l"(p));
    return a;
}
__device__ __forceinline__ void ldsm_x4(uint32_t a[4], uint32_t addr) {
    asm volatile("ldmatrix.sync.aligned.m8n8.x4.shared.b16 {%0,%1,%2,%3}, [%4];"
        : "=r"(a[0]), "=r"(a[1]), "=r"(a[2]), "=r"(a[3]) : "r"(addr));
}
__device__ __forceinline__ void mma16816(float d[4], const uint32_t a[4],
                                         const uint32_t b[2]) {
    asm volatile("mma.sync.aligned.m16n8k16.row.col.f32.f16.f16.f32 "
        "{%0,%1,%2,%3}, {%4,%5,%6,%7}, {%8,%9}, {%0,%1,%2,%3};"
        : "+f"(d[0]), "+f"(d[1]), "+f"(d[2]), "+f"(d[3])
        : "r"(a[0]), "r"(a[1]), "r"(a[2]), "r"(a[3]), "r"(b[0]), "r"(b[1]));
}

// tanh: MUFU.TANH. Sigmoid of original z = fmaf(0.5, tanh(z/2), 0.5), where
// z/2 comes out of the MMA directly (gates i,f,o pre-scaled by 0.5).
__device__ __forceinline__ float ftanh(float x) {
    float r;
    asm("tanh.approx.f32 %0, %1;" : "=f"(r) : "f"(x));
    return r;
}
__device__ __forceinline__ float fsig_pre(float half_z) {
    return fmaf(0.5f, ftanh(half_z), 0.5f);
}

// C[48x32] += A[48x128] * B[32x128]^T. Per k16: 2 B-ldsm.x4 + 3 A-ldsm.x4,
// 12 MMAs. B fragments reused across the 3 m-tiles.
__device__ __forceinline__ void mma_tile48(uint32_t aAddr, uint32_t bAddr4,
                                           float acc[3][4][4]) {
    #pragma unroll
    for (int k0 = 0; k0 < 8; k0++) {
        uint32_t b0[4], b1[4];
        ldsm_x4(b0, bAddr4 + k0 * 32);
        ldsm_x4(b1, bAddr4 + 16 * ROWSTR + k0 * 32);
        #pragma unroll
        for (int mt = 0; mt < 3; mt++) {
            uint32_t a[4];
            ldsm_x4(a, aAddr + mt * 16 * ROWSTR + k0 * 32);
            mma16816(acc[mt][0], a, b0);
            mma16816(acc[mt][1], a, b0 + 2);
            mma16816(acc[mt][2], a, b1);
            mma16816(acc[mt][3], a, b1 + 2);
        }
    }
}

// init acc from the 6 gathered fp16 P rows of this thread
__device__ __forceinline__ void loadP(float acc[3][4][4], const int srow[6],
                                      int gcq) {
    #pragma unroll
    for (int mt = 0; mt < 3; mt++) {
        const __half* p0 = g_P16 + (size_t)srow[2 * mt]     * 512 + gcq;
        const __half* p1 = g_P16 + (size_t)srow[2 * mt + 1] * 512 + gcq;
        #pragma unroll
        for (int nt = 0; nt < 4; nt++) {
            half2 v0 = __ldg((const half2*)(p0 + nt * 8));
            half2 v1 = __ldg((const half2*)(p1 + nt * 8));
            acc[mt][nt][0] = __low2float(v0); acc[mt][nt][1] = __high2float(v0);
            acc[mt][nt][2] = __low2float(v1); acc[mt][nt][3] = __high2float(v1);
        }
    }
}

// gate scale: 0.5 for i(0), f(1), o(3); 1.0 for g(2)
__device__ __forceinline__ float gate_scale(int gate) {
    return (gate == 2) ? 1.0f : 0.5f;
}

// ---------------------------------------------------------------------------
// p_mma_kernel: P = scale_g * (Xin @ Wih^T + (bih+bhh)) on HMMA, fp16 out.
// ---------------------------------------------------------------------------
__global__ void __launch_bounds__(LTH, 1)
p_mma_kernel(const float* __restrict__ Xin,
             const float* __restrict__ Wih,   // [512,128]
             const float* __restrict__ bih,   // [512]
             const float* __restrict__ bhh)   // [512]
{
    extern __shared__ char smc[];
    const uint32_t sb = smem_u32(smc);

    const int tid  = threadIdx.x;
    const int wid  = tid >> 5;
    const int lane = tid & 31;
    const int g8   = lane >> 2;
    const int q    = lane & 3;
    const int m0   = (wid % 3) * 48;
    const int n0   = (wid / 3) * 32;
    const int nblk = blockIdx.x * MCTA;

    // load Wih (4 gate tiles) fp32->fp16, pre-scaled per gate
    for (int idx = tid; idx < 512 * 64; idx += LTH) {
        int rg = idx >> 6, cp = idx & 63;
        int gate = rg >> 7, row = rg & 127, col = cp * 2;
        float sc = gate_scale(gate);
        float2 v = *(const float2*)(Wih + (size_t)rg * 128 + col);
        v.x *= sc; v.y *= sc;
        *(half2*)(smc + SM_PW + gate * WTILE_B + row * ROWSTR + col * 2) =
            __float22half2_rn(v);
    }
    // load X tile fp32->fp16 (clamp OOB rows)
    for (int idx = tid; idx < MCTA * 64; idx += LTH) {
        int row = idx >> 6, cp = idx & 63, col = cp * 2;
        int n = nblk + row; if (n >= NN) n = NN - 1;
        float2 v = *(const float2*)(Xin + (size_t)n * FDIM + col);
        *(half2*)(smc + SM_X + row * ROWSTR + col * 2) = __float22half2_rn(v);
    }
    __syncthreads();

    const uint32_t aX = sb + SM_X + (m0 + (lane & 15)) * ROWSTR + ((lane >> 4) * 16);
    const uint32_t bW = sb + SM_PW + (n0 + (lane & 7) + ((lane >> 4) << 3)) * ROWSTR +
                        (((lane >> 3) & 1) * 16);

    #pragma unroll 1
    for (int g = 0; g < 4; g++) {
        const float sc = gate_scale(g);
        float acc[3][4][4];
        #pragma unroll
        for (int nt = 0; nt < 4; nt++) {
            int col = g * 128 + n0 + nt * 8 + q * 2;
            float b0 = sc * (__ldg(bih + col)     + __ldg(bhh + col));
            float b1 = sc * (__ldg(bih + col + 1) + __ldg(bhh + col + 1));
            #pragma unroll
            for (int mt = 0; mt < 3; mt++) {
                acc[mt][nt][0] = b0; acc[mt][nt][1] = b1;
                acc[mt][nt][2] = b0; acc[mt][nt][3] = b1;
            }
        }
        mma_tile48(aX, bW + g * WTILE_B, acc);

        #pragma unroll
        for (int mt = 0; mt < 3; mt++) {
            const int node0 = nblk + m0 + mt * 16 + g8;
            const int node1 = node0 + 8;
            #pragma unroll
            for (int nt = 0; nt < 4; nt++) {
                const int col = g * 128 + n0 + nt * 8 + q * 2;
                if (node0 < NN)
                    *(half2*)(g_P16 + (size_t)node0 * 512 + col) =
                        __floats2half2_rn(acc[mt][nt][0], acc[mt][nt][1]);
                if (node1 < NN)
                    *(half2*)(g_P16 + (size_t)node1 * 512 + col) =
                        __floats2half2_rn(acc[mt][nt][2], acc[mt][nt][3]);
            }
        }
    }
}

// ---------------------------------------------------------------------------
// lstm_mma_kernel: CTA = 144 nodes, 12 warps (48x32 tiles); gates i, g, f, o.
// Carried state PACKED: tmp and c both half2 (fp32 math, fp16 storage).
// ---------------------------------------------------------------------------
__global__ void __launch_bounds__(LTH, 1)
lstm_mma_kernel(const float* __restrict__ Xin,
                float* __restrict__ Xout,
                const int* __restrict__ src,
                const float* __restrict__ Whh,   // [512,128]
                const float* __restrict__ Wl,    // [outdim,128]
                const float* __restrict__ bl,    // [outdim]
                const float* __restrict__ Wr,    // [outdim,128]
                int outdim, int do_relu, int do_res)
{
    extern __shared__ char smc[];
    const uint32_t sb = smem_u32(smc);
    int* sSrc0 = (int*)(smc);
    int* sSrc1 = (int*)(smc + 640);

    const int tid  = threadIdx.x;
    const int wid  = tid >> 5;
    const int lane = tid & 31;
    const int g8   = lane >> 2;
    const int q    = lane & 3;
    const int m0   = (wid % 3) * 48;
    const int n0   = (wid / 3) * 32;
    const int nblk = blockIdx.x * MCTA;

    const uint32_t aLane = (m0 + (lane & 15)) * ROWSTR + ((lane >> 4) * 16);
    const uint32_t aH0   = sb + SM_H0 + aLane;
    const uint32_t aH1   = sb + SM_H1 + aLane;
    const uint32_t bW    = sb + SM_W +
                           (n0 + (lane & 7) + ((lane >> 4) << 3)) * ROWSTR +
                           (((lane >> 3) & 1) * 16);

    // Whh fp32->fp16, pre-scaled per gate
    for (int idx = tid; idx < 512 * 64; idx += LTH) {
        int rg = idx >> 6, cp = idx & 63;
        int gate = rg >> 7, row = rg & 127, col = cp * 2;
        float sc = gate_scale(gate);
        float2 v = *(const float2*)(Whh + (size_t)rg * 128 + col);
        v.x *= sc; v.y *= sc;
        *(half2*)(smc + SM_W + gate * WTILE_B + row * ROWSTR + col * 2) =
            __float22half2_rn(v);
    }
    for (int idx = tid; idx < HTILE_B / 16; idx += LTH)
        ((uint4*)(smc + SM_H0))[idx] = make_uint4(0u, 0u, 0u, 0u);
    if (tid < MCTA) {
        int n = nblk + tid;
        sSrc0[tid] = (n < NN) ? __ldg(src + n * DEG) : 0;
    }
    __syncthreads();

    half2 cc[3][4][2];    // packed cell state
    {
        const half2 z = __float2half2_rn(0.0f);
        #pragma unroll
        for (int mt = 0; mt < 3; mt++)
            #pragma unroll
            for (int nt = 0; nt < 4; nt++) {
                cc[mt][nt][0] = z; cc[mt][nt][1] = z;
            }
    }

    #pragma unroll 1
    for (int t = 0; t < DEG; t++) {
        const int* sCur   = (t & 1) ? sSrc1 : sSrc0;
        int*       sNext  = (t & 1) ? sSrc0 : sSrc1;
        const uint32_t aH = (t & 1) ? aH1 : aH0;
        char*      hNext  = (t & 1) ? (smc + SM_H0) : (smc + SM_H1);

        const int cq = n0 + q * 2;
        int srow[6];
        #pragma unroll
        for (int mt = 0; mt < 3; mt++) {
            srow[2 * mt]     = sCur[m0 + mt * 16 + g8];
            srow[2 * mt + 1] = sCur[m0 + mt * 16 + g8 + 8];
        }

        float acc[3][4][4];
        half2 tmp[3][4][2];   // packed transient: sig(i), then sig(i)*tanh(g)

        // -- gate i (z/2): tmp = sigmoid (packed fp16) --
        loadP(acc, srow, 0 * 128 + cq);
        mma_tile48(aH, bW + 0 * WTILE_B, acc);
        #pragma unroll
        for (int mt = 0; mt < 3; mt++)
            #pragma unroll
            for (int nt = 0; nt < 4; nt++) {
                tmp[mt][nt][0] = __floats2half2_rn(fsig_pre(acc[mt][nt][0]),
                                                   fsig_pre(acc[mt][nt][1]));
                tmp[mt][nt][1] = __floats2half2_rn(fsig_pre(acc[mt][nt][2]),
                                                   fsig_pre(acc[mt][nt][3]));
            }

        // -- gate g (unscaled): tmp *= tanh (packed fp16) --
        loadP(acc, srow, 2 * 128 + cq);
        mma_tile48(aH, bW + 2 * WTILE_B, acc);
        #pragma unroll
        for (int mt = 0; mt < 3; mt++)
            #pragma unroll
            for (int nt = 0; nt < 4; nt++) {
                tmp[mt][nt][0] = __hmul2(tmp[mt][nt][0],
                    __floats2half2_rn(ftanh(acc[mt][nt][0]),
                                      ftanh(acc[mt][nt][1])));
                tmp[mt][nt][1] = __hmul2(tmp[mt][nt][1],
                    __floats2half2_rn(ftanh(acc[mt][nt][2]),
                                      ftanh(acc[mt][nt][3])));
            }

        // -- gate f (z/2): c = sigmoid*c + tmp  (fp32 math, fp16 store) --
        loadP(acc, srow, 1 * 128 + cq);
        mma_tile48(aH, bW + 1 * WTILE_B, acc);
        #pragma unroll
        for (int mt = 0; mt < 3; mt++)
            #pragma unroll
            for (int nt = 0; nt < 4; nt++) {
                float c0 = fmaf(fsig_pre(acc[mt][nt][0]),
                                __low2float(cc[mt][nt][0]),
                                __low2float(tmp[mt][nt][0]));
                float c1 = fmaf(fsig_pre(acc[mt][nt][1]),
                                __high2float(cc[mt][nt][0]),
                                __high2float(tmp[mt][nt][0]));
                float c2 = fmaf(fsig_pre(acc[mt][nt][2]),
                                __low2float(cc[mt][nt][1]),
                                __low2float(tmp[mt][nt][1]));
                float c3 = fmaf(fsig_pre(acc[mt][nt][3]),
                                __high2float(cc[mt][nt][1]),
                                __high2float(tmp[mt][nt][1]));
                cc[mt][nt][0] = __floats2half2_rn(c0, c1);
                cc[mt][nt][1] = __floats2half2_rn(c2, c3);
            }

        // -- gate o (z/2): raw half-pre-activation stays in acc --
        loadP(acc, srow, 3 * 128 + cq);
        mma_tile48(aH, bW + 3 * WTILE_B, acc);

        // h = sigmoid(o)*tanh(c) -> other H buffer
        #pragma unroll
        for (int mt = 0; mt < 3; mt++) {
            const int row = m0 + mt * 16 + g8;
            #pragma unroll
            for (int nt = 0; nt < 4; nt++) {
                const int colb = (n0 + nt * 8 + q * 2) * 2;
                half2 h0 = __floats2half2_rn(
                    fsig_pre(acc[mt][nt][0]) * ftanh(__low2float(cc[mt][nt][0])),
                    fsig_pre(acc[mt][nt][1]) * ftanh(__high2float(cc[mt][nt][0])));
                half2 h1 = __floats2half2_rn(
                    fsig_pre(acc[mt][nt][2]) * ftanh(__low2float(cc[mt][nt][1])),
                    fsig_pre(acc[mt][nt][3]) * ftanh(__high2float(cc[mt][nt][1])));
                *(half2*)(hNext + row * ROWSTR + colb)       = h0;
                *(half2*)(hNext + (row + 8) * ROWSTR + colb) = h1;
            }
        }
        if (tid < MCTA && t + 1 < DEG) {
            int n = nblk + tid;
            sNext[tid] = (n < NN) ? __ldg(src + n * DEG + t + 1) : 0;
        }
        __syncthreads();
    }
    // final H in buffer H0 (DEG even)

    // ---- projections: out = H@Wl^T + bl + X@Wr^T (+res)(relu) --------------
    // slot0 <- Wl, slot1 <- Wr (zero-padded rows>=outdim), slot2(+3) <- X fp16
    {
        const half2 z = __float2half2_rn(0.0f);
        for (int idx = tid; idx < MCTA * 64; idx += LTH) {
            int row = idx >> 6, cp = idx & 63, col = cp * 2;
            if (row < 128) {
                half2 vl = z, vr = z;
                if (row < outdim) {
                    vl = __float22half2_rn(*(const float2*)(Wl + (size_t)row * 128 + col));
                    vr = __float22half2_rn(*(const float2*)(Wr + (size_t)row * 128 + col));
                }
                int off = row * ROWSTR + col * 2;
                *(half2*)(smc + SM_W + off)           = vl;
                *(half2*)(smc + SM_W + WTILE_B + off) = vr;
            }
            int n = nblk + row; if (n >= NN) n = NN - 1;
            *(half2*)(smc + SM_W + 2 * WTILE_B + row * ROWSTR + col * 2) =
                __float22half2_rn(*(const float2*)(Xin + (size_t)n * 128 + col));
        }
    }
    __syncthreads();

    float acc[3][4][4];
    #pragma unroll
    for (int mt = 0; mt < 3; mt++) {
        const int node0 = nblk + m0 + mt * 16 + g8, node1 = node0 + 8;
        #pragma unroll
        for (int nt = 0; nt < 4; nt++) {
            const int colp = n0 + nt * 8 + q * 2;
            float b0 = 0.f, b1 = 0.f;
            if (colp < outdim) { b0 = __ldg(bl + colp); b1 = __ldg(bl + colp + 1); }
            float x00 = 0.f, x01 = 0.f, x10 = 0.f, x11 = 0.f;
            if (do_res) {
                if (node0 < NN) {
                    float2 v = *(const float2*)(Xin + (size_t)node0 * 128 + colp);
                    x00 = v.x; x01 = v.y;
                }
                if (node1 < NN) {
                    float2 v = *(const float2*)(Xin + (size_t)node1 * 128 + colp);
                    x10 = v.x; x11 = v.y;
                }
            }
            acc[mt][nt][0] = b0 + x00; acc[mt][nt][1] = b1 + x01;
            acc[mt][nt][2] = b0 + x10; acc[mt][nt][3] = b1 + x11;
        }
    }

    mma_tile48(aH0, bW + 0 * WTILE_B, acc);                    // H @ Wl^T
    mma_tile48(sb + SM_W + 2 * WTILE_B + aLane,
               bW + 1 * WTILE_B, acc);                         // X @ Wr^T

    #pragma unroll
    for (int mt = 0; mt < 3; mt++) {
        const int node0 = nblk + m0 + mt * 16 + g8, node1 = node0 + 8;
        #pragma unroll
        for (int nt = 0; nt < 4; nt++) {
            const int colp = n0 + nt * 8 + q * 2;
            if (colp >= outdim) continue;
            float v0 = acc[mt][nt][0], v1 = acc[mt][nt][1];
            float v2 = acc[mt][nt][2], v3 = acc[mt][nt][3];
            if (do_relu) {
                v0 = fmaxf(v0, 0.f); v1 = fmaxf(v1, 0.f);
                v2 = fmaxf(v2, 0.f); v3 = fmaxf(v3, 0.f);
            }
            if (node0 < NN)
                *(float2*)(Xout + (size_t)node0 * outdim + colp) = make_float2(v0, v1);
            if (node1 < NN)
                *(float2*)(Xout + (size_t)node1 * outdim + colp) = make_float2(v2, v3);
        }
    }
}

// ---------------------------------------------------------------------------
static void run_layer(const float* Xin, float* Xout, const int* src,
                      const float* Wih, const float* Whh,
                      const float* bih, const float* bhh,
                      const float* Wl, const float* bl, const float* Wr,
                      int outdim, int do_relu, int do_res)
{
    p_mma_kernel<<<NCTA2, LTH, SMEM_PM>>>(Xin, Wih, bih, bhh);
    lstm_mma_kernel<<<NCTA2, LTH, SMEM_L>>>(Xin, Xout, src, Whh, Wl, bl, Wr,
                                            outdim, do_relu, do_res);
}

extern "C" void kernel_launch(void* const* d_in, const int* in_sizes, int n_in,
                              void* d_out, int out_size)
{
    (void)in_sizes; (void)n_in; (void)out_size;
    const float* x     = (const float*)d_in[0];
    const int*   src   = (const int*)  d_in[1];
    const float* Wih   = (const float*)d_in[2];   // [4,512,128]
    const float* Whh   = (const float*)d_in[3];   // [4,512,128]
    const float* bih   = (const float*)d_in[4];   // [4,512]
    const float* bhh   = (const float*)d_in[5];   // [4,512]
    const float* Wl123 = (const float*)d_in[6];   // [3,128,128]
    const float* bl123 = (const float*)d_in[7];   // [3,128]
    const float* Wr123 = (const float*)d_in[8];   // [3,128,128]
    const float* Wl4   = (const float*)d_in[9];   // [64,128]
    const float* bl4   = (const float*)d_in[10];  // [64]
    const float* Wr4   = (const float*)d_in[11];  // [64,128]
    float*       out   = (float*)d_out;           // [N,64]

    cudaFuncSetAttribute(p_mma_kernel,
        cudaFuncAttributeMaxDynamicSharedMemorySize, (int)SMEM_PM);
    cudaFuncSetAttribute(lstm_mma_kernel,
        cudaFuncAttributeMaxDynamicSharedMemorySize, (int)SMEM_L);

    float *xa = nullptr, *xb = nullptr;
    cudaGetSymbolAddress((void**)&xa, g_XA);
    cudaGetSymbolAddress((void**)&xb, g_XB);

    run_layer(x,  xa, src, Wih + 0 * 512 * 128, Whh + 0 * 512 * 128,
              bih + 0 * 512, bhh + 0 * 512,
              Wl123 + 0 * 128 * 128, bl123 + 0 * 128, Wr123 + 0 * 128 * 128,
              128, 1, 0);
    run_layer(xa, xb, src, Wih + 1 * 512 * 128, Whh + 1 * 512 * 128,
              bih + 1 * 512, bhh + 1 * 512,
              Wl123 + 1 * 128 * 128, bl123 + 1 * 128, Wr123 + 1 * 128 * 128,
              128, 1, 1);
    run_layer(xb, xa, src, Wih + 2 * 512 * 128, Whh + 2 * 512 * 128,
              bih + 2 * 512, bhh + 2 * 512,
              Wl123 + 2 * 128 * 128, bl123 + 2 * 128, Wr123 + 2 * 128 * 128,
              128, 1, 1);
    run_layer(xa, out, src, Wih + 3 * 512 * 128, Whh + 3 * 512 * 128,
              bih + 3 * 512, bhh + 3 * 512,
              Wl4, bl4, Wr4,
              64, 0, 0);
}

// round 15
// speedup vs baseline: 1.1945x; 1.1945x over previous
#include <cuda_runtime.h>
#include <cuda_fp16.h>
#include <cstdint>
#include <cstddef>

// ============================================================================
// ImprovedGraphSAGE via portable mma.sync (HMMA) — sm_100-safe (no tcgen05).
//   p_mma_kernel : P = Xin @ Wih^T + (bih+bhh)  (HMMA, fp16 store)
//                  gates i,f,o PRE-SCALED by 0.5 (sigmoid-via-tanh trick)
//   lstm_mma     : 16-step LSTM; H @ Whh^T on HMMA; fused projections.
// R15: R12 base (MCTA=48, 16x32 tiles — the only non-spilling shape) with
//      GATE PAIRING: (i,g) and (f,o) fused into single k-loops sharing the
//      A fragment and exposing TWO independent MMA chains per warp
//      (latency-bound kernel -> ~2x ILP; -17% ldsm).
// ============================================================================

#define NN   20000
#define DEG  16
#define FDIM 128

#define MCTA    48                         // nodes per CTA
#define NCTA2   ((NN + MCTA - 1) / MCTA)   // 417
#define LTH     384                        // 12 warps: 3 rowgroups x 4 colgroups
#define ROWSTR  272                        // fp16 row stride bytes (ldmatrix-safe)
#define HTILE_B (MCTA * ROWSTR)            // 13056
#define WTILE_B (128 * ROWSTR)             // 34816

// lstm SMEM map
#define SM_H0   1024
#define SM_H1   (SM_H0 + HTILE_B)
#define SM_W    (SM_H1 + HTILE_B)          // 27136
#define SMEM_L  (SM_W + 4 * WTILE_B)       // 166400

// p_mma SMEM map
#define SM_X    1024
#define SM_PW   (SM_X + HTILE_B)
#define SMEM_PM (SM_PW + 4 * WTILE_B)      // 153344

__device__ __half g_P16[(size_t)NN * 512];
__device__ float  g_XA [(size_t)NN * FDIM];
__device__ float  g_XB [(size_t)NN * FDIM];

// ---------------------------------------------------------------------------
__device__ __forceinline__ uint32_t smem_u32(const void* p) {
    uint32_t a;
    asm("{ .reg .u64 t; cvta.to.shared.u64 t, %1; cvt.u32.u64 %0, t; }"
        : "=r"(a) : "l"(p));
    return a;
}
__device__ __forceinline__ void ldsm_x4(uint32_t a[4], uint32_t addr) {
    asm volatile("ldmatrix.sync.aligned.m8n8.x4.shared.b16 {%0,%1,%2,%3}, [%4];"
        : "=r"(a[0]), "=r"(a[1]), "=r"(a[2]), "=r"(a[3]) : "r"(addr));
}
__device__ __forceinline__ void mma16816(float d[4], const uint32_t a[4],
                                         const uint32_t b[2]) {
    asm volatile("mma.sync.aligned.m16n8k16.row.col.f32.f16.f16.f32 "
        "{%0,%1,%2,%3}, {%4,%5,%6,%7}, {%8,%9}, {%0,%1,%2,%3};"
        : "+f"(d[0]), "+f"(d[1]), "+f"(d[2]), "+f"(d[3])
        : "r"(a[0]), "r"(a[1]), "r"(a[2]), "r"(a[3]), "r"(b[0]), "r"(b[1]));
}

// tanh: MUFU.TANH. Sigmoid of original z = fmaf(0.5, tanh(z/2), 0.5), where
// z/2 comes out of the MMA directly (gates i,f,o pre-scaled by 0.5).
__device__ __forceinline__ float ftanh(float x) {
    float r;
    asm("tanh.approx.f32 %0, %1;" : "=f"(r) : "f"(x));
    return r;
}
__device__ __forceinline__ float fsig_pre(float half_z) {
    return fmaf(0.5f, ftanh(half_z), 0.5f);
}

// Single-gate tile: C[16x32] += A[16x128] * B[32x128]^T (used in epilogue).
__device__ __forceinline__ void mma_tile16(uint32_t aAddr, uint32_t bAddr4,
                                           float acc[4][4]) {
    #pragma unroll
    for (int k0 = 0; k0 < 8; k0++) {
        uint32_t a[4];
        ldsm_x4(a, aAddr + k0 * 32);
        #pragma unroll
        for (int np = 0; np < 2; np++) {
            uint32_t b[4];
            ldsm_x4(b, bAddr4 + np * 16 * ROWSTR + k0 * 32);
            mma16816(acc[2 * np],     a, b);
            mma16816(acc[2 * np + 1], a, b + 2);
        }
    }
}

// PAIRED gates: one k-loop, shared A fragment, TWO independent MMA chains.
// Per k16: 1 A + 4 B x4-loads, 8 MMAs (4 per gate).
__device__ __forceinline__ void mma_pair(uint32_t aAddr,
                                         uint32_t b1Addr, uint32_t b2Addr,
                                         float acc1[4][4], float acc2[4][4]) {
    #pragma unroll
    for (int k0 = 0; k0 < 8; k0++) {
        uint32_t a[4];
        ldsm_x4(a, aAddr + k0 * 32);
        uint32_t b1a[4], b1b[4], b2a[4], b2b[4];
        ldsm_x4(b1a, b1Addr + k0 * 32);
        ldsm_x4(b2a, b2Addr + k0 * 32);
        ldsm_x4(b1b, b1Addr + 16 * ROWSTR + k0 * 32);
        ldsm_x4(b2b, b2Addr + 16 * ROWSTR + k0 * 32);
        mma16816(acc1[0], a, b1a);
        mma16816(acc2[0], a, b2a);
        mma16816(acc1[1], a, b1a + 2);
        mma16816(acc2[1], a, b2a + 2);
        mma16816(acc1[2], a, b1b);
        mma16816(acc2[2], a, b2b);
        mma16816(acc1[3], a, b1b + 2);
        mma16816(acc2[3], a, b2b + 2);
    }
}

// Issue the 8 gathered P loads for one gate (deferred consumption).
__device__ __forceinline__ void loadPh(half2 pv0[4], half2 pv1[4],
                                       const __half* p0, const __half* p1,
                                       int goff) {
    #pragma unroll
    for (int nt = 0; nt < 4; nt++) {
        pv0[nt] = __ldg((const half2*)(p0 + goff + nt * 8));
        pv1[nt] = __ldg((const half2*)(p1 + goff + nt * 8));
    }
}
__device__ __forceinline__ void zacc(float acc[4][4]) {
    #pragma unroll
    for (int nt = 0; nt < 4; nt++)
        #pragma unroll
        for (int e = 0; e < 4; e++) acc[nt][e] = 0.0f;
}
// Gate pre-activation element (MMA result + deferred P term)
__device__ __forceinline__ float gp(const float a[4], const half2 pv0,
                                    const half2 pv1, int e) {
    float p = (e == 0) ? __low2float(pv0) : (e == 1) ? __high2float(pv0)
            : (e == 2) ? __low2float(pv1) : __high2float(pv1);
    return a[e] + p;
}

// gate scale: 0.5 for i(0), f(1), o(3); 1.0 for g(2)
__device__ __forceinline__ float gate_scale(int gate) {
    return (gate == 2) ? 1.0f : 0.5f;
}

// ---------------------------------------------------------------------------
// p_mma_kernel: P = scale_g * (Xin @ Wih^T + (bih+bhh)) on HMMA, fp16 out.
// ---------------------------------------------------------------------------
__global__ void __launch_bounds__(LTH, 1)
p_mma_kernel(const float* __restrict__ Xin,
             const float* __restrict__ Wih,   // [512,128]
             const float* __restrict__ bih,   // [512]
             const float* __restrict__ bhh)   // [512]
{
    extern __shared__ char smc[];
    const uint32_t sb = smem_u32(smc);

    const int tid  = threadIdx.x;
    const int wid  = tid >> 5;
    const int lane = tid & 31;
    const int g8   = lane >> 2;
    const int q    = lane & 3;
    const int m0   = (wid % 3) * 16;
    const int n0   = (wid / 3) * 32;
    const int nblk = blockIdx.x * MCTA;

    // load Wih (4 gate tiles) fp32->fp16, pre-scaled per gate
    for (int idx = tid; idx < 512 * 64; idx += LTH) {
        int rg = idx >> 6, cp = idx & 63;
        int gate = rg >> 7, row = rg & 127, col = cp * 2;
        float sc = gate_scale(gate);
        float2 v = *(const float2*)(Wih + (size_t)rg * 128 + col);
        v.x *= sc; v.y *= sc;
        *(half2*)(smc + SM_PW + gate * WTILE_B + row * ROWSTR + col * 2) =
            __float22half2_rn(v);
    }
    // load X tile fp32->fp16 (clamp OOB rows)
    for (int idx = tid; idx < MCTA * 64; idx += LTH) {
        int row = idx >> 6, cp = idx & 63, col = cp * 2;
        int n = nblk + row; if (n >= NN) n = NN - 1;
        float2 v = *(const float2*)(Xin + (size_t)n * FDIM + col);
        *(half2*)(smc + SM_X + row * ROWSTR + col * 2) = __float22half2_rn(v);
    }
    __syncthreads();

    const uint32_t aX    = sb + SM_X + (m0 + (lane & 15)) * ROWSTR + ((lane >> 4) * 16);
    const uint32_t bOff4 = (n0 + (lane & 7) + ((lane >> 4) << 3)) * ROWSTR +
                           (((lane >> 3) & 1) * 16);

    #pragma unroll 1
    for (int g = 0; g < 4; g++) {
        const float sc = gate_scale(g);
        float acc[4][4];
        #pragma unroll
        for (int nt = 0; nt < 4; nt++) {
            int col = g * 128 + n0 + nt * 8 + q * 2;
            float b0 = sc * (__ldg(bih + col)     + __ldg(bhh + col));
            float b1 = sc * (__ldg(bih + col + 1) + __ldg(bhh + col + 1));
            acc[nt][0] = b0; acc[nt][1] = b1;
            acc[nt][2] = b0; acc[nt][3] = b1;
        }
        mma_tile16(aX, sb + SM_PW + g * WTILE_B + bOff4, acc);

        // d[0..1] -> row m0+g8, d[2..3] -> row m0+g8+8
        const int node0 = nblk + m0 + g8;
        const int node1 = node0 + 8;
        #pragma unroll
        for (int nt = 0; nt < 4; nt++) {
            const int col = g * 128 + n0 + nt * 8 + q * 2;
            if (node0 < NN)
                *(half2*)(g_P16 + (size_t)node0 * 512 + col) =
                    __floats2half2_rn(acc[nt][0], acc[nt][1]);
            if (node1 < NN)
                *(half2*)(g_P16 + (size_t)node1 * 512 + col) =
                    __floats2half2_rn(acc[nt][2], acc[nt][3]);
        }
    }
}

// ---------------------------------------------------------------------------
// lstm_mma_kernel: CTA = 48 nodes, 12 warps (16x32 tiles).
// Gate pairs (i,g) then (f,o), each pair one fused k-loop with 2 MMA chains.
// ---------------------------------------------------------------------------
__global__ void __launch_bounds__(LTH, 1)
lstm_mma_kernel(const float* __restrict__ Xin,
                float* __restrict__ Xout,
                const int* __restrict__ src,
                const float* __restrict__ Whh,   // [512,128]
                const float* __restrict__ Wl,    // [outdim,128]
                const float* __restrict__ bl,    // [outdim]
                const float* __restrict__ Wr,    // [outdim,128]
                int outdim, int do_relu, int do_res)
{
    extern __shared__ char smc[];
    const uint32_t sb = smem_u32(smc);
    int* sSrc0 = (int*)(smc);
    int* sSrc1 = (int*)(smc + 512);

    const int tid  = threadIdx.x;
    const int wid  = tid >> 5;
    const int lane = tid & 31;
    const int g8   = lane >> 2;
    const int q    = lane & 3;
    const int m0   = (wid % 3) * 16;
    const int n0   = (wid / 3) * 32;
    const int nblk = blockIdx.x * MCTA;

    const uint32_t aLane = (m0 + (lane & 15)) * ROWSTR + ((lane >> 4) * 16);
    const uint32_t aH0   = sb + SM_H0 + aLane;
    const uint32_t aH1   = sb + SM_H1 + aLane;
    const uint32_t bOff4 = (n0 + (lane & 7) + ((lane >> 4) << 3)) * ROWSTR +
                           (((lane >> 3) & 1) * 16);

    // Whh fp32->fp16, pre-scaled per gate
    for (int idx = tid; idx < 512 * 64; idx += LTH) {
        int rg = idx >> 6, cp = idx & 63;
        int gate = rg >> 7, row = rg & 127, col = cp * 2;
        float sc = gate_scale(gate);
        float2 v = *(const float2*)(Whh + (size_t)rg * 128 + col);
        v.x *= sc; v.y *= sc;
        *(half2*)(smc + SM_W + gate * WTILE_B + row * ROWSTR + col * 2) =
            __float22half2_rn(v);
    }
    for (int idx = tid; idx < HTILE_B / 16; idx += LTH)
        ((uint4*)(smc + SM_H0))[idx] = make_uint4(0u, 0u, 0u, 0u);
    if (tid < MCTA) {
        int n = nblk + tid;
        sSrc0[tid] = (n < NN) ? __ldg(src + n * DEG) : 0;
    }
    __syncthreads();

    float c[4][4];
    #pragma unroll
    for (int nt = 0; nt < 4; nt++)
        #pragma unroll
        for (int e = 0; e < 4; e++) c[nt][e] = 0.0f;

    #pragma unroll 1
    for (int t = 0; t < DEG; t++) {
        const int* sCur   = (t & 1) ? sSrc1 : sSrc0;
        int*       sNext  = (t & 1) ? sSrc0 : sSrc1;
        const uint32_t aH = (t & 1) ? aH1 : aH0;
        char*      hNext  = (t & 1) ? (smc + SM_H0) : (smc + SM_H1);

        const int cq = n0 + q * 2;
        const __half* p0 = g_P16 + (size_t)sCur[m0 + g8]     * 512 + cq;
        const __half* p1 = g_P16 + (size_t)sCur[m0 + g8 + 8] * 512 + cq;

        float accA[4][4], accB[4][4], tmp[4][4];
        half2 pvA0[4], pvA1[4], pvB0[4], pvB1[4];

        // ---- pair 1: gates i (slot 0) and g (slot 2) ----
        loadPh(pvA0, pvA1, p0, p1, 0 * 128);
        loadPh(pvB0, pvB1, p0, p1, 2 * 128);
        zacc(accA); zacc(accB);
        mma_pair(aH, sb + SM_W + 0 * WTILE_B + bOff4,
                     sb + SM_W + 2 * WTILE_B + bOff4, accA, accB);
        #pragma unroll
        for (int nt = 0; nt < 4; nt++)
            #pragma unroll
            for (int e = 0; e < 4; e++)
                tmp[nt][e] = fsig_pre(gp(accA[nt], pvA0[nt], pvA1[nt], e)) *
                             ftanh(gp(accB[nt], pvB0[nt], pvB1[nt], e));

        // ---- pair 2: gates f (slot 1) and o (slot 3) ----
        loadPh(pvA0, pvA1, p0, p1, 1 * 128);
        loadPh(pvB0, pvB1, p0, p1, 3 * 128);
        zacc(accA); zacc(accB);
        mma_pair(aH, sb + SM_W + 1 * WTILE_B + bOff4,
                     sb + SM_W + 3 * WTILE_B + bOff4, accA, accB);
        #pragma unroll
        for (int nt = 0; nt < 4; nt++)
            #pragma unroll
            for (int e = 0; e < 4; e++)
                c[nt][e] = fmaf(fsig_pre(gp(accA[nt], pvA0[nt], pvA1[nt], e)),
                                c[nt][e], tmp[nt][e]);

        // h = sigmoid(o)*tanh(c) -> other H buffer
        {
            const int row = m0 + g8;
            #pragma unroll
            for (int nt = 0; nt < 4; nt++) {
                const int colb = (n0 + nt * 8 + q * 2) * 2;
                half2 h0 = __floats2half2_rn(
                    fsig_pre(gp(accB[nt], pvB0[nt], pvB1[nt], 0)) * ftanh(c[nt][0]),
                    fsig_pre(gp(accB[nt], pvB0[nt], pvB1[nt], 1)) * ftanh(c[nt][1]));
                half2 h1 = __floats2half2_rn(
                    fsig_pre(gp(accB[nt], pvB0[nt], pvB1[nt], 2)) * ftanh(c[nt][2]),
                    fsig_pre(gp(accB[nt], pvB0[nt], pvB1[nt], 3)) * ftanh(c[nt][3]));
                *(half2*)(hNext + row * ROWSTR + colb)       = h0;
                *(half2*)(hNext + (row + 8) * ROWSTR + colb) = h1;
            }
        }
        if (tid < MCTA && t + 1 < DEG) {
            int n = nblk + tid;
            sNext[tid] = (n < NN) ? __ldg(src + n * DEG + t + 1) : 0;
        }
        __syncthreads();
    }
    // final H in buffer H0 (DEG even)

    // ---- projections: out = H@Wl^T + bl + X@Wr^T (+res)(relu) --------------
    {
        const half2 z = __float2half2_rn(0.0f);
        for (int idx = tid; idx < 128 * 64; idx += LTH) {
            int row = idx >> 6, cp = idx & 63, col = cp * 2;
            half2 vl = z, vr = z;
            if (row < outdim) {
                vl = __float22half2_rn(*(const float2*)(Wl + (size_t)row * 128 + col));
                vr = __float22half2_rn(*(const float2*)(Wr + (size_t)row * 128 + col));
            }
            int off = row * ROWSTR + col * 2;
            *(half2*)(smc + SM_W + off)           = vl;
            *(half2*)(smc + SM_W + WTILE_B + off) = vr;
            if (row < MCTA) {
                int n = nblk + row; if (n >= NN) n = NN - 1;
                *(half2*)(smc + SM_W + 2 * WTILE_B + off) =
                    __float22half2_rn(*(const float2*)(Xin + (size_t)n * 128 + col));
            }
        }
    }
    __syncthreads();

    float acc[4][4];
    {
        const int node0 = nblk + m0 + g8, node1 = node0 + 8;
        #pragma unroll
        for (int nt = 0; nt < 4; nt++) {
            const int colp = n0 + nt * 8 + q * 2;
            float b0 = 0.f, b1 = 0.f;
            if (colp < outdim) { b0 = __ldg(bl + colp); b1 = __ldg(bl + colp + 1); }
            float x00 = 0.f, x01 = 0.f, x10 = 0.f, x11 = 0.f;
            if (do_res) {
                if (node0 < NN) {
                    float2 v = *(const float2*)(Xin + (size_t)node0 * 128 + colp);
                    x00 = v.x; x01 = v.y;
                }
                if (node1 < NN) {
                    float2 v = *(const float2*)(Xin + (size_t)node1 * 128 + colp);
                    x10 = v.x; x11 = v.y;
                }
            }
            acc[nt][0] = b0 + x00; acc[nt][1] = b1 + x01;
            acc[nt][2] = b0 + x10; acc[nt][3] = b1 + x11;
        }
    }

    mma_tile16(aH0, sb + SM_W + 0 * WTILE_B + bOff4, acc);                 // H @ Wl^T
    mma_tile16(sb + SM_W + 2 * WTILE_B + aLane,
               sb + SM_W + 1 * WTILE_B + bOff4, acc);                      // X @ Wr^T

    {
        const int node0 = nblk + m0 + g8, node1 = node0 + 8;
        #pragma unroll
        for (int nt = 0; nt < 4; nt++) {
            const int colp = n0 + nt * 8 + q * 2;
            if (colp >= outdim) continue;
            float v0 = acc[nt][0], v1 = acc[nt][1];
            float v2 = acc[nt][2], v3 = acc[nt][3];
            if (do_relu) {
                v0 = fmaxf(v0, 0.f); v1 = fmaxf(v1, 0.f);
                v2 = fmaxf(v2, 0.f); v3 = fmaxf(v3, 0.f);
            }
            if (node0 < NN)
                *(float2*)(Xout + (size_t)node0 * outdim + colp) = make_float2(v0, v1);
            if (node1 < NN)
                *(float2*)(Xout + (size_t)node1 * outdim + colp) = make_float2(v2, v3);
        }
    }
}

// ---------------------------------------------------------------------------
static void run_layer(const float* Xin, float* Xout, const int* src,
                      const float* Wih, const float* Whh,
                      const float* bih, const float* bhh,
                      const float* Wl, const float* bl, const float* Wr,
                      int outdim, int do_relu, int do_res)
{
    p_mma_kernel<<<NCTA2, LTH, SMEM_PM>>>(Xin, Wih, bih, bhh);
    lstm_mma_kernel<<<NCTA2, LTH, SMEM_L>>>(Xin, Xout, src, Whh, Wl, bl, Wr,
                                            outdim, do_relu, do_res);
}

extern "C" void kernel_launch(void* const* d_in, const int* in_sizes, int n_in,
                              void* d_out, int out_size)
{
    (void)in_sizes; (void)n_in; (void)out_size;
    const float* x     = (const float*)d_in[0];
    const int*   src   = (const int*)  d_in[1];
    const float* Wih   = (const float*)d_in[2];   // [4,512,128]
    const float* Whh   = (const float*)d_in[3];   // [4,512,128]
    const float* bih   = (const float*)d_in[4];   // [4,512]
    const float* bhh   = (const float*)d_in[5];   // [4,512]
    const float* Wl123 = (const float*)d_in[6];   // [3,128,128]
    const float* bl123 = (const float*)d_in[7];   // [3,128]
    const float* Wr123 = (const float*)d_in[8];   // [3,128,128]
    const float* Wl4   = (const float*)d_in[9];   // [64,128]
    const float* bl4   = (const float*)d_in[10];  // [64]
    const float* Wr4   = (const float*)d_in[11];  // [64,128]
    float*       out   = (float*)d_out;           // [N,64]

    cudaFuncSetAttribute(p_mma_kernel,
        cudaFuncAttributeMaxDynamicSharedMemorySize, (int)SMEM_PM);
    cudaFuncSetAttribute(lstm_mma_kernel,
        cudaFuncAttributeMaxDynamicSharedMemorySize, (int)SMEM_L);

    float *xa = nullptr, *xb = nullptr;
    cudaGetSymbolAddress((void**)&xa, g_XA);
    cudaGetSymbolAddress((void**)&xb, g_XB);

    run_layer(x,  xa, src, Wih + 0 * 512 * 128, Whh + 0 * 512 * 128,
              bih + 0 * 512, bhh + 0 * 512,
              Wl123 + 0 * 128 * 128, bl123 + 0 * 128, Wr123 + 0 * 128 * 128,
              128, 1, 0);
    run_layer(xa, xb, src, Wih + 1 * 512 * 128, Whh + 1 * 512 * 128,
              bih + 1 * 512, bhh + 1 * 512,
              Wl123 + 1 * 128 * 128, bl123 + 1 * 128, Wr123 + 1 * 128 * 128,
              128, 1, 1);
    run_layer(xb, xa, src, Wih + 2 * 512 * 128, Whh + 2 * 512 * 128,
              bih + 2 * 512, bhh + 2 * 512,
              Wl123 + 2 * 128 * 128, bl123 + 2 * 128, Wr123 + 2 * 128 * 128,
              128, 1, 1);
    run_layer(xa, out, src, Wih + 3 * 512 * 128, Whh + 3 * 512 * 128,
              bih + 3 * 512, bhh + 3 * 512,
              Wl4, bl4, Wr4,
              64, 0, 0);
}